// round 13
// baseline (speedup 1.0000x reference)
#include <cuda_runtime.h>
#include <cuda_fp16.h>
#include <stdint.h>

#define BB 4
#define SS 2048
#define DD 1024
#define DVV 64
#define SCALE 0.125f      // 1/sqrt(64)
#define LNEPS 1e-6f
#define OUT_ELEMS (BB*SS*DD)

// GEMM tiling: CTA 128x256x128, 256 threads, 8 warps 2(M)x4(N), warp tile 64x64
#define BM 128
#define BN 256
#define BK 128
#define KITERS (DD/BK)            // 8
#define A_OFF 0
#define B_OFF 32768               // A = 128*256B = 32KB
#define STAGE 98304               // + B = 256*256B = 64KB
#define SMEM_DYN (2*STAGE + 1024)

// scratch (no allocations allowed)
__device__ __half g_qh[BB*SS*DD];
__device__ __half g_kh[BB*SS*DD];
__device__ float g_w[DD];

// ---------------------------------------------------------------- helpers
__device__ __forceinline__ uint32_t smem_u32(const void* p) {
    uint32_t a;
    asm("{ .reg .u64 t; cvta.to.shared.u64 t, %1; cvt.u32.u64 %0, t; }"
        : "=r"(a) : "l"(p));
    return a;
}
// swizzle for 256B-pitch rows
#define SWZ(o) ((o) ^ (((o) >> 4) & 0x70))

__device__ __forceinline__ void cpa16(uint32_t dst, const void* src) {
    asm volatile("cp.async.cg.shared.global [%0], [%1], 16;" :: "r"(dst), "l"(src) : "memory");
}
__device__ __forceinline__ void ldsm4(uint32_t* r, uint32_t addr) {
    asm volatile("ldmatrix.sync.aligned.m8n8.x4.shared.b16 {%0,%1,%2,%3}, [%4];"
                 : "=r"(r[0]), "=r"(r[1]), "=r"(r[2]), "=r"(r[3]) : "r"(addr));
}
__device__ __forceinline__ void mma_f16(float* d, const uint32_t* a, const uint32_t* b) {
    asm volatile(
        "mma.sync.aligned.m16n8k16.row.col.f32.f16.f16.f32 "
        "{%0,%1,%2,%3}, {%4,%5,%6,%7}, {%8,%9}, {%0,%1,%2,%3};"
        : "+f"(d[0]), "+f"(d[1]), "+f"(d[2]), "+f"(d[3])
        : "r"(a[0]), "r"(a[1]), "r"(a[2]), "r"(a[3]), "r"(b[0]), "r"(b[1]));
}

// ---------------------------------------------------------------------------
__global__ void k_w(const float* __restrict__ fc_w, const float* __restrict__ V) {
    int d = blockIdx.x * blockDim.x + threadIdx.x;
    if (d < DD) {
        float s = 0.f;
        #pragma unroll
        for (int i = 0; i < DVV; i++) s += fc_w[d * DVV + i] * V[i];
        g_w[d] = s;
    }
}

// ---------------------------------------------------------------------------
// LayerNorm + scale -> fp16. One block (256 thr) per row of 1024.
__global__ void k_ln(const float* __restrict__ q,
                     const float* __restrict__ lng,
                     const float* __restrict__ lnb) {
    int row = blockIdx.x;
    const float4* x4 = (const float4*)(q + (size_t)row * DD);
    float4 v = x4[threadIdx.x];
    float sum = v.x + v.y + v.z + v.w;
    float sq  = v.x * v.x + v.y * v.y + v.z * v.z + v.w * v.w;

    __shared__ float ssum[8], ssq[8];
    __shared__ float s_mu, s_rstd;
    #pragma unroll
    for (int off = 16; off > 0; off >>= 1) {
        sum += __shfl_down_sync(0xffffffffu, sum, off);
        sq  += __shfl_down_sync(0xffffffffu, sq,  off);
    }
    int wid = threadIdx.x >> 5, lid = threadIdx.x & 31;
    if (lid == 0) { ssum[wid] = sum; ssq[wid] = sq; }
    __syncthreads();
    if (threadIdx.x == 0) {
        float ts = 0.f, tq = 0.f;
        #pragma unroll
        for (int i = 0; i < 8; i++) { ts += ssum[i]; tq += ssq[i]; }
        float mu  = ts * (1.0f / DD);
        float var = tq * (1.0f / DD) - mu * mu;
        s_mu = mu;
        s_rstd = rsqrtf(var + LNEPS);
    }
    __syncthreads();
    float mu = s_mu, rs = s_rstd;
    float4 g4 = ((const float4*)lng)[threadIdx.x];
    float4 b4 = ((const float4*)lnb)[threadIdx.x];
    __half h[4];
    h[0] = __float2half(((v.x - mu) * rs * g4.x + b4.x) * SCALE);
    h[1] = __float2half(((v.y - mu) * rs * g4.y + b4.y) * SCALE);
    h[2] = __float2half(((v.z - mu) * rs * g4.z + b4.z) * SCALE);
    h[3] = __float2half(((v.w - mu) * rs * g4.w + b4.w) * SCALE);
    *(uint2*)&g_qh[(size_t)row * DD + threadIdx.x * 4] = *(uint2*)h;
}

// ---------------------------------------------------------------------------
__global__ void k_conv(const float* __restrict__ x) {
    size_t i = ((size_t)blockIdx.x * blockDim.x + threadIdx.x) * 4;
    float4 v = *(const float4*)(x + i);
    __half h[4];
    h[0] = __float2half(v.x);
    h[1] = __float2half(v.y);
    h[2] = __float2half(v.z);
    h[3] = __float2half(v.w);
    *(uint2*)&g_kh[i] = *(uint2*)h;
}

// ---------------------------------------------------------------------------
// Warp-MMA GEMM: attn = qs @ k^T (fp16), masked on write.
// CTA 128x256x128, 8 warps 2(M)x4(N), warp tile 64x64. 2-stage cp.async.
__global__ __launch_bounds__(256, 1)
void k_gemm(const int* __restrict__ mask, float* __restrict__ attn) {
    extern __shared__ char dsm[];
    uint32_t sbase = (smem_u32(dsm) + 1023u) & ~1023u;

    int tid = threadIdx.x, wid = tid >> 5, lane = tid & 31;
    int b = blockIdx.z, bm = blockIdx.y * BM, bn = blockIdx.x * BN;

    const __half* Ah = g_qh + (size_t)b * SS * DD;
    const __half* Bh = g_kh + (size_t)b * SS * DD;

    int j = tid & 15;         // 16B chunk within 256B row
    int r0 = tid >> 4;        // 0..15

    #define LOAD_STAGE(SB, K0) do {                                            \
        uint32_t _sb = (SB); int _k0 = (K0);                                   \
        _Pragma("unroll")                                                      \
        for (int it = 0; it < 8; it++) {                                       \
            int r = r0 + it * 16;                                              \
            uint32_t so = SWZ((uint32_t)(r * 256 + j * 16));                   \
            cpa16(_sb + A_OFF + so, Ah + (size_t)(bm + r) * DD + _k0 + j * 8); \
        }                                                                      \
        _Pragma("unroll")                                                      \
        for (int it = 0; it < 16; it++) {                                      \
            int r = r0 + it * 16;                                              \
            uint32_t so = SWZ((uint32_t)(r * 256 + j * 16));                   \
            cpa16(_sb + B_OFF + so, Bh + (size_t)(bn + r) * DD + _k0 + j * 8); \
        }                                                                      \
        asm volatile("cp.async.commit_group;" ::: "memory");                   \
    } while (0)

    float acc[4][8][4];
    #pragma unroll
    for (int i = 0; i < 4; i++)
        #pragma unroll
        for (int n = 0; n < 8; n++)
            #pragma unroll
            for (int c = 0; c < 4; c++) acc[i][n][c] = 0.f;

    int wm = (wid & 1) * 64;          // warp M offset in tile
    int wn = (wid >> 1) * 64;         // warp N offset in tile

    int a_r = (lane & 7) + ((lane >> 3) & 1) * 8;
    int a_k = (lane >> 4) * 16;
    int b_r = (lane & 7) + (lane >> 4) * 8;
    int b_k = ((lane >> 3) & 1) * 16;

    LOAD_STAGE(sbase, 0);
    LOAD_STAGE(sbase + STAGE, BK);

    for (int kt = 0; kt < KITERS; kt++) {
        if (kt == KITERS - 1) asm volatile("cp.async.wait_group 0;" ::: "memory");
        else                  asm volatile("cp.async.wait_group 1;" ::: "memory");
        __syncthreads();
        uint32_t sb = sbase + (kt & 1) * STAGE;

        #pragma unroll
        for (int ks = 0; ks < 8; ks++) {
            int kb = ks * 32;             // k16 = 32 bytes
            uint32_t a[4][4], bf[4][4];
            #pragma unroll
            for (int mt = 0; mt < 4; mt++) {
                uint32_t off = SWZ((uint32_t)((wm + mt * 16 + a_r) * 256 + kb + a_k));
                ldsm4(a[mt], sb + A_OFF + off);
            }
            #pragma unroll
            for (int bt = 0; bt < 4; bt++) {
                uint32_t off = SWZ((uint32_t)((wn + bt * 16 + b_r) * 256 + kb + b_k));
                ldsm4(bf[bt], sb + B_OFF + off);
            }
            #pragma unroll
            for (int mt = 0; mt < 4; mt++) {
                #pragma unroll
                for (int nt = 0; nt < 8; nt++) {
                    mma_f16(acc[mt][nt], a[mt], &bf[nt >> 1][(nt & 1) * 2]);
                }
            }
        }
        __syncthreads();
        if (kt + 2 < KITERS) LOAD_STAGE(sbase + (kt & 1) * STAGE, (kt + 2) * BK);
    }

    // epilogue: masked write of attn
    size_t abase = (size_t)b * SS * SS;
    int qr = lane >> 2, qc = (lane & 3) * 2;
    #pragma unroll
    for (int mt = 0; mt < 4; mt++) {
        int row1 = bm + wm + mt * 16 + qr;
        size_t ro1 = abase + (size_t)row1 * SS;
        size_t ro2 = ro1 + 8 * SS;
        #pragma unroll
        for (int nt = 0; nt < 8; nt++) {
            int col = bn + wn + nt * 8 + qc;
            int2 m1 = *(const int2*)&mask[ro1 + col];
            int2 m2 = *(const int2*)&mask[ro2 + col];
            float2 o1, o2;
            o1.x = m1.x ? 0.f : acc[mt][nt][0];
            o1.y = m1.y ? 0.f : acc[mt][nt][1];
            o2.x = m2.x ? 0.f : acc[mt][nt][2];
            o2.y = m2.y ? 0.f : acc[mt][nt][3];
            *(float2*)&attn[ro1 + col] = o1;
            *(float2*)&attn[ro2 + col] = o2;
        }
    }
}

// ---------------------------------------------------------------------------
// rowsum(attn row) then output = rowsum*w + fc_b + q. One block per (b,s).
__global__ void k_out(const float* __restrict__ attn,
                      const float* __restrict__ q,
                      const float* __restrict__ fc_b,
                      float* __restrict__ out) {
    int rid = blockIdx.x;
    const float4* row = (const float4*)(attn + (size_t)rid * SS);
    float s = 0.f;
    #pragma unroll
    for (int i = 0; i < 2; i++) {
        float4 v = row[threadIdx.x + i * 256];
        s += v.x + v.y + v.z + v.w;
    }
    __shared__ float sh[8];
    __shared__ float s_total;
    #pragma unroll
    for (int off = 16; off > 0; off >>= 1)
        s += __shfl_down_sync(0xffffffffu, s, off);
    int wid = threadIdx.x >> 5, lid = threadIdx.x & 31;
    if (lid == 0) sh[wid] = s;
    __syncthreads();
    if (threadIdx.x == 0) {
        float t = 0.f;
        #pragma unroll
        for (int i = 0; i < 8; i++) t += sh[i];
        s_total = t;
    }
    __syncthreads();
    float rs = s_total;
    float4 w4 = ((const float4*)g_w)[threadIdx.x];
    float4 b4 = ((const float4*)fc_b)[threadIdx.x];
    float4 q4 = ((const float4*)(q + (size_t)rid * DD))[threadIdx.x];
    float4 o;
    o.x = rs * w4.x + b4.x + q4.x;
    o.y = rs * w4.y + b4.y + q4.y;
    o.z = rs * w4.z + b4.z + q4.z;
    o.w = rs * w4.w + b4.w + q4.w;
    ((float4*)(out + (size_t)rid * DD))[threadIdx.x] = o;
}

// ---------------------------------------------------------------------------
extern "C" void kernel_launch(void* const* d_in, const int* in_sizes, int n_in,
                              void* d_out, int out_size) {
    const float* q    = (const float*)d_in[0];
    const float* kmat = (const float*)d_in[1];
    const int*   mask = (const int*)d_in[3];
    const float* V    = (const float*)d_in[4];
    const float* fc_w = (const float*)d_in[5];
    const float* fc_b = (const float*)d_in[6];
    const float* ln_g = (const float*)d_in[7];
    const float* ln_b = (const float*)d_in[8];

    float* out  = (float*)d_out;
    float* attn = out + OUT_ELEMS;

    cudaFuncSetAttribute(k_gemm, cudaFuncAttributeMaxDynamicSharedMemorySize, SMEM_DYN);

    k_w<<<4, 256>>>(fc_w, V);
    k_ln<<<BB * SS, 256>>>(q, ln_g, ln_b);
    k_conv<<<(BB * SS * DD / 4) / 256, 256>>>(kmat);
    dim3 g(SS / BN, SS / BM, BB);
    k_gemm<<<g, 256, SMEM_DYN>>>(mask, attn);
    k_out<<<BB * SS, 256>>>(attn, q, fc_b, out);
}

// round 14
// speedup vs baseline: 1.1179x; 1.1179x over previous
#include <cuda_runtime.h>
#include <cuda_fp16.h>
#include <stdint.h>

#define BB 4
#define SS 2048
#define DD 1024
#define DVV 64
#define SCALE 0.125f      // 1/sqrt(64)
#define LNEPS 1e-6f
#define OUT_ELEMS (BB*SS*DD)

// GEMM tiling: CTA 128x128x64, 256 threads, 8 warps 2(M)x4(N), warp tile 64x32
// 2 CTAs per SM (smem 64KB/CTA, regs capped at 128).
#define BM 128
#define BN 128
#define BK 64
#define KITERS (DD/BK)            // 16
#define A_OFF 0
#define B_OFF 16384               // A = 128*128B = 16KB
#define STAGE 32768               // + B = 16KB
#define SMEM_DYN (2*STAGE + 1024)

// scratch (no allocations allowed)
__device__ __half g_qh[BB*SS*DD];
__device__ __half g_kh[BB*SS*DD];
__device__ float g_w[DD];

// ---------------------------------------------------------------- helpers
__device__ __forceinline__ uint32_t smem_u32(const void* p) {
    uint32_t a;
    asm("{ .reg .u64 t; cvta.to.shared.u64 t, %1; cvt.u32.u64 %0, t; }"
        : "=r"(a) : "l"(p));
    return a;
}
// swizzle for 128B-pitch rows
#define SWZ(o) ((o) ^ (((o) >> 3) & 0x70))

__device__ __forceinline__ void cpa16(uint32_t dst, const void* src) {
    asm volatile("cp.async.cg.shared.global [%0], [%1], 16;" :: "r"(dst), "l"(src) : "memory");
}
__device__ __forceinline__ void ldsm4(uint32_t* r, uint32_t addr) {
    asm volatile("ldmatrix.sync.aligned.m8n8.x4.shared.b16 {%0,%1,%2,%3}, [%4];"
                 : "=r"(r[0]), "=r"(r[1]), "=r"(r[2]), "=r"(r[3]) : "r"(addr));
}
__device__ __forceinline__ void mma_f16(float* d, const uint32_t* a, const uint32_t* b) {
    asm volatile(
        "mma.sync.aligned.m16n8k16.row.col.f32.f16.f16.f32 "
        "{%0,%1,%2,%3}, {%4,%5,%6,%7}, {%8,%9}, {%0,%1,%2,%3};"
        : "+f"(d[0]), "+f"(d[1]), "+f"(d[2]), "+f"(d[3])
        : "r"(a[0]), "r"(a[1]), "r"(a[2]), "r"(a[3]), "r"(b[0]), "r"(b[1]));
}

// ---------------------------------------------------------------------------
__global__ void k_w(const float* __restrict__ fc_w, const float* __restrict__ V) {
    int d = blockIdx.x * blockDim.x + threadIdx.x;
    if (d < DD) {
        float s = 0.f;
        #pragma unroll
        for (int i = 0; i < DVV; i++) s += fc_w[d * DVV + i] * V[i];
        g_w[d] = s;
    }
}

// ---------------------------------------------------------------------------
// LayerNorm + scale -> fp16. One block (256 thr) per row of 1024.
__global__ void k_ln(const float* __restrict__ q,
                     const float* __restrict__ lng,
                     const float* __restrict__ lnb) {
    int row = blockIdx.x;
    const float4* x4 = (const float4*)(q + (size_t)row * DD);
    float4 v = x4[threadIdx.x];
    float sum = v.x + v.y + v.z + v.w;
    float sq  = v.x * v.x + v.y * v.y + v.z * v.z + v.w * v.w;

    __shared__ float ssum[8], ssq[8];
    __shared__ float s_mu, s_rstd;
    #pragma unroll
    for (int off = 16; off > 0; off >>= 1) {
        sum += __shfl_down_sync(0xffffffffu, sum, off);
        sq  += __shfl_down_sync(0xffffffffu, sq,  off);
    }
    int wid = threadIdx.x >> 5, lid = threadIdx.x & 31;
    if (lid == 0) { ssum[wid] = sum; ssq[wid] = sq; }
    __syncthreads();
    if (threadIdx.x == 0) {
        float ts = 0.f, tq = 0.f;
        #pragma unroll
        for (int i = 0; i < 8; i++) { ts += ssum[i]; tq += ssq[i]; }
        float mu  = ts * (1.0f / DD);
        float var = tq * (1.0f / DD) - mu * mu;
        s_mu = mu;
        s_rstd = rsqrtf(var + LNEPS);
    }
    __syncthreads();
    float mu = s_mu, rs = s_rstd;
    float4 g4 = ((const float4*)lng)[threadIdx.x];
    float4 b4 = ((const float4*)lnb)[threadIdx.x];
    __half h[4];
    h[0] = __float2half(((v.x - mu) * rs * g4.x + b4.x) * SCALE);
    h[1] = __float2half(((v.y - mu) * rs * g4.y + b4.y) * SCALE);
    h[2] = __float2half(((v.z - mu) * rs * g4.z + b4.z) * SCALE);
    h[3] = __float2half(((v.w - mu) * rs * g4.w + b4.w) * SCALE);
    *(uint2*)&g_qh[(size_t)row * DD + threadIdx.x * 4] = *(uint2*)h;
}

// ---------------------------------------------------------------------------
__global__ void k_conv(const float* __restrict__ x) {
    size_t i = ((size_t)blockIdx.x * blockDim.x + threadIdx.x) * 4;
    float4 v = *(const float4*)(x + i);
    __half h[4];
    h[0] = __float2half(v.x);
    h[1] = __float2half(v.y);
    h[2] = __float2half(v.z);
    h[3] = __float2half(v.w);
    *(uint2*)&g_kh[i] = *(uint2*)h;
}

// ---------------------------------------------------------------------------
// Warp-MMA GEMM: attn = qs @ k^T (fp16), masked on write.
// CTA 128x128x64, 8 warps 2(M)x4(N), warp tile 64x32. 2-stage cp.async,
// 2 CTAs per SM.
__global__ __launch_bounds__(256, 2)
void k_gemm(const int* __restrict__ mask, float* __restrict__ attn) {
    extern __shared__ char dsm[];
    uint32_t sbase = (smem_u32(dsm) + 1023u) & ~1023u;

    int tid = threadIdx.x, wid = tid >> 5, lane = tid & 31;
    int b = blockIdx.z, bm = blockIdx.y * BM, bn = blockIdx.x * BN;

    const __half* Ah = g_qh + (size_t)b * SS * DD;
    const __half* Bh = g_kh + (size_t)b * SS * DD;

    int j = tid & 7;          // 16B chunk within 128B row
    int r0 = tid >> 3;        // 0..31

    #define LOAD_STAGE(SB, K0) do {                                            \
        uint32_t _sb = (SB); int _k0 = (K0);                                   \
        _Pragma("unroll")                                                      \
        for (int it = 0; it < 4; it++) {                                       \
            int r = r0 + it * 32;                                              \
            uint32_t so = SWZ((uint32_t)(r * 128 + j * 16));                   \
            cpa16(_sb + A_OFF + so, Ah + (size_t)(bm + r) * DD + _k0 + j * 8); \
            cpa16(_sb + B_OFF + so, Bh + (size_t)(bn + r) * DD + _k0 + j * 8); \
        }                                                                      \
        asm volatile("cp.async.commit_group;" ::: "memory");                   \
    } while (0)

    float acc[4][4][4];
    #pragma unroll
    for (int i = 0; i < 4; i++)
        #pragma unroll
        for (int n = 0; n < 4; n++)
            #pragma unroll
            for (int c = 0; c < 4; c++) acc[i][n][c] = 0.f;

    int wm = (wid & 1) * 64;          // warp M offset in tile
    int wn = (wid >> 1) * 32;         // warp N offset in tile

    int a_r = (lane & 7) + ((lane >> 3) & 1) * 8;
    int a_k = (lane >> 4) * 16;
    int b_r = (lane & 7) + (lane >> 4) * 8;
    int b_k = ((lane >> 3) & 1) * 16;

    LOAD_STAGE(sbase, 0);
    LOAD_STAGE(sbase + STAGE, BK);

    for (int kt = 0; kt < KITERS; kt++) {
        if (kt == KITERS - 1) asm volatile("cp.async.wait_group 0;" ::: "memory");
        else                  asm volatile("cp.async.wait_group 1;" ::: "memory");
        __syncthreads();
        uint32_t sb = sbase + (kt & 1) * STAGE;

        #pragma unroll
        for (int ks = 0; ks < 4; ks++) {
            int kb = ks * 32;             // k16 = 32 bytes
            uint32_t a[4][4], bf[2][4];
            #pragma unroll
            for (int mt = 0; mt < 4; mt++) {
                uint32_t off = SWZ((uint32_t)((wm + mt * 16 + a_r) * 128 + kb + a_k));
                ldsm4(a[mt], sb + A_OFF + off);
            }
            #pragma unroll
            for (int bt = 0; bt < 2; bt++) {
                uint32_t off = SWZ((uint32_t)((wn + bt * 16 + b_r) * 128 + kb + b_k));
                ldsm4(bf[bt], sb + B_OFF + off);
            }
            #pragma unroll
            for (int mt = 0; mt < 4; mt++) {
                #pragma unroll
                for (int nt = 0; nt < 4; nt++) {
                    mma_f16(acc[mt][nt], a[mt], &bf[nt >> 1][(nt & 1) * 2]);
                }
            }
        }
        __syncthreads();
        if (kt + 2 < KITERS) LOAD_STAGE(sbase + (kt & 1) * STAGE, (kt + 2) * BK);
    }

    // epilogue: masked write of attn
    size_t abase = (size_t)b * SS * SS;
    int qr = lane >> 2, qc = (lane & 3) * 2;
    #pragma unroll
    for (int mt = 0; mt < 4; mt++) {
        int row1 = bm + wm + mt * 16 + qr;
        size_t ro1 = abase + (size_t)row1 * SS;
        size_t ro2 = ro1 + 8 * SS;
        #pragma unroll
        for (int nt = 0; nt < 4; nt++) {
            int col = bn + wn + nt * 8 + qc;
            int2 m1 = *(const int2*)&mask[ro1 + col];
            int2 m2 = *(const int2*)&mask[ro2 + col];
            float2 o1, o2;
            o1.x = m1.x ? 0.f : acc[mt][nt][0];
            o1.y = m1.y ? 0.f : acc[mt][nt][1];
            o2.x = m2.x ? 0.f : acc[mt][nt][2];
            o2.y = m2.y ? 0.f : acc[mt][nt][3];
            *(float2*)&attn[ro1 + col] = o1;
            *(float2*)&attn[ro2 + col] = o2;
        }
    }
}

// ---------------------------------------------------------------------------
// rowsum(attn row) then output = rowsum*w + fc_b + q. One block per (b,s).
__global__ void k_out(const float* __restrict__ attn,
                      const float* __restrict__ q,
                      const float* __restrict__ fc_b,
                      float* __restrict__ out) {
    int rid = blockIdx.x;
    const float4* row = (const float4*)(attn + (size_t)rid * SS);
    float s = 0.f;
    #pragma unroll
    for (int i = 0; i < 2; i++) {
        float4 v = row[threadIdx.x + i * 256];
        s += v.x + v.y + v.z + v.w;
    }
    __shared__ float sh[8];
    __shared__ float s_total;
    #pragma unroll
    for (int off = 16; off > 0; off >>= 1)
        s += __shfl_down_sync(0xffffffffu, s, off);
    int wid = threadIdx.x >> 5, lid = threadIdx.x & 31;
    if (lid == 0) sh[wid] = s;
    __syncthreads();
    if (threadIdx.x == 0) {
        float t = 0.f;
        #pragma unroll
        for (int i = 0; i < 8; i++) t += sh[i];
        s_total = t;
    }
    __syncthreads();
    float rs = s_total;
    float4 w4 = ((const float4*)g_w)[threadIdx.x];
    float4 b4 = ((const float4*)fc_b)[threadIdx.x];
    float4 q4 = ((const float4*)(q + (size_t)rid * DD))[threadIdx.x];
    float4 o;
    o.x = rs * w4.x + b4.x + q4.x;
    o.y = rs * w4.y + b4.y + q4.y;
    o.z = rs * w4.z + b4.z + q4.z;
    o.w = rs * w4.w + b4.w + q4.w;
    ((float4*)(out + (size_t)rid * DD))[threadIdx.x] = o;
}

// ---------------------------------------------------------------------------
extern "C" void kernel_launch(void* const* d_in, const int* in_sizes, int n_in,
                              void* d_out, int out_size) {
    const float* q    = (const float*)d_in[0];
    const float* kmat = (const float*)d_in[1];
    const int*   mask = (const int*)d_in[3];
    const float* V    = (const float*)d_in[4];
    const float* fc_w = (const float*)d_in[5];
    const float* fc_b = (const float*)d_in[6];
    const float* ln_g = (const float*)d_in[7];
    const float* ln_b = (const float*)d_in[8];

    float* out  = (float*)d_out;
    float* attn = out + OUT_ELEMS;

    cudaFuncSetAttribute(k_gemm, cudaFuncAttributeMaxDynamicSharedMemorySize, SMEM_DYN);

    k_w<<<4, 256>>>(fc_w, V);
    k_ln<<<BB * SS, 256>>>(q, ln_g, ln_b);
    k_conv<<<(BB * SS * DD / 4) / 256, 256>>>(kmat);
    dim3 g(SS / BN, SS / BM, BB);
    k_gemm<<<g, 256, SMEM_DYN>>>(mask, attn);
    k_out<<<BB * SS, 256>>>(attn, q, fc_b, out);
}

// round 16
// speedup vs baseline: 1.1937x; 1.0678x over previous
#include <cuda_runtime.h>
#include <cuda_fp16.h>
#include <stdint.h>

#define BB 4
#define SS 2048
#define DD 1024
#define DVV 64
#define SCALE 0.125f      // 1/sqrt(64)
#define LNEPS 1e-6f
#define OUT_ELEMS (BB*SS*DD)

// GEMM tiling: CTA 128x128x64, 256 threads, 8 warps 2(M)x4(N), warp tile 64x32
// 2 CTAs per SM (smem 66KB/CTA, regs capped at 128).
#define BM 128
#define BN 128
#define BK 64
#define KITERS (DD/BK)            // 16
#define A_OFF 0
#define B_OFF 16384               // A = 128*128B = 16KB
#define STAGE 32768               // + B = 16KB
#define ROWSUM_OFF (2*STAGE)
#define SMEM_DYN (2*STAGE + 512 + 1024)

// scratch (no allocations allowed)
__device__ __half g_qh[BB*SS*DD];
__device__ __half g_kh[BB*SS*DD];
__device__ float g_w[DD];
__device__ float g_rowsum[BB*SS];

// ---------------------------------------------------------------- helpers
__device__ __forceinline__ uint32_t smem_u32(const void* p) {
    uint32_t a;
    asm("{ .reg .u64 t; cvta.to.shared.u64 t, %1; cvt.u32.u64 %0, t; }"
        : "=r"(a) : "l"(p));
    return a;
}
// swizzle for 128B-pitch rows
#define SWZ(o) ((o) ^ (((o) >> 3) & 0x70))

__device__ __forceinline__ void cpa16(uint32_t dst, const void* src) {
    asm volatile("cp.async.cg.shared.global [%0], [%1], 16;" :: "r"(dst), "l"(src) : "memory");
}
__device__ __forceinline__ void ldsm4(uint32_t* r, uint32_t addr) {
    asm volatile("ldmatrix.sync.aligned.m8n8.x4.shared.b16 {%0,%1,%2,%3}, [%4];"
                 : "=r"(r[0]), "=r"(r[1]), "=r"(r[2]), "=r"(r[3]) : "r"(addr));
}
__device__ __forceinline__ void mma_f16(float* d, const uint32_t* a, const uint32_t* b) {
    asm volatile(
        "mma.sync.aligned.m16n8k16.row.col.f32.f16.f16.f32 "
        "{%0,%1,%2,%3}, {%4,%5,%6,%7}, {%8,%9}, {%0,%1,%2,%3};"
        : "+f"(d[0]), "+f"(d[1]), "+f"(d[2]), "+f"(d[3])
        : "r"(a[0]), "r"(a[1]), "r"(a[2]), "r"(a[3]), "r"(b[0]), "r"(b[1]));
}

// ---------------------------------------------------------------------------
__global__ void k_w(const float* __restrict__ fc_w, const float* __restrict__ V) {
    int d = blockIdx.x * blockDim.x + threadIdx.x;
    if (d < DD) {
        float s = 0.f;
        #pragma unroll
        for (int i = 0; i < DVV; i++) s += fc_w[d * DVV + i] * V[i];
        g_w[d] = s;
    }
}

// ---------------------------------------------------------------------------
// LayerNorm + scale -> fp16. One block (256 thr) per row of 1024.
// Also zeroes g_rowsum for the fused-rowsum GEMM epilogue.
__global__ void k_ln(const float* __restrict__ q,
                     const float* __restrict__ lng,
                     const float* __restrict__ lnb) {
    int row = blockIdx.x;
    if (threadIdx.x == 0) g_rowsum[row] = 0.f;
    const float4* x4 = (const float4*)(q + (size_t)row * DD);
    float4 v = x4[threadIdx.x];
    float sum = v.x + v.y + v.z + v.w;
    float sq  = v.x * v.x + v.y * v.y + v.z * v.z + v.w * v.w;

    __shared__ float ssum[8], ssq[8];
    __shared__ float s_mu, s_rstd;
    #pragma unroll
    for (int off = 16; off > 0; off >>= 1) {
        sum += __shfl_down_sync(0xffffffffu, sum, off);
        sq  += __shfl_down_sync(0xffffffffu, sq,  off);
    }
    int wid = threadIdx.x >> 5, lid = threadIdx.x & 31;
    if (lid == 0) { ssum[wid] = sum; ssq[wid] = sq; }
    __syncthreads();
    if (threadIdx.x == 0) {
        float ts = 0.f, tq = 0.f;
        #pragma unroll
        for (int i = 0; i < 8; i++) { ts += ssum[i]; tq += ssq[i]; }
        float mu  = ts * (1.0f / DD);
        float var = tq * (1.0f / DD) - mu * mu;
        s_mu = mu;
        s_rstd = rsqrtf(var + LNEPS);
    }
    __syncthreads();
    float mu = s_mu, rs = s_rstd;
    float4 g4 = ((const float4*)lng)[threadIdx.x];
    float4 b4 = ((const float4*)lnb)[threadIdx.x];
    __half h[4];
    h[0] = __float2half(((v.x - mu) * rs * g4.x + b4.x) * SCALE);
    h[1] = __float2half(((v.y - mu) * rs * g4.y + b4.y) * SCALE);
    h[2] = __float2half(((v.z - mu) * rs * g4.z + b4.z) * SCALE);
    h[3] = __float2half(((v.w - mu) * rs * g4.w + b4.w) * SCALE);
    *(uint2*)&g_qh[(size_t)row * DD + threadIdx.x * 4] = *(uint2*)h;
}

// ---------------------------------------------------------------------------
__global__ void k_conv(const float* __restrict__ x) {
    size_t i = ((size_t)blockIdx.x * blockDim.x + threadIdx.x) * 4;
    float4 v = *(const float4*)(x + i);
    __half h[4];
    h[0] = __float2half(v.x);
    h[1] = __float2half(v.y);
    h[2] = __float2half(v.z);
    h[3] = __float2half(v.w);
    *(uint2*)&g_kh[i] = *(uint2*)h;
}

// ---------------------------------------------------------------------------
// Warp-MMA GEMM: attn = qs @ k^T (fp16), masked on write, fused rowsum.
// CTA 128x128x64, 8 warps 2(M)x4(N), warp tile 64x32. 2-stage cp.async,
// 2 CTAs per SM. LDS bases hoisted; per-ks step applies kb via XOR
// (SWZ(x+kb) == SWZ(x)^kb when pre-swizzle bits 5-6 of x are clear).
__global__ __launch_bounds__(256, 2)
void k_gemm(const int* __restrict__ mask, float* __restrict__ attn) {
    extern __shared__ char dsm[];
    uint32_t sbase = (smem_u32(dsm) + 1023u) & ~1023u;
    float* smrow = (float*)(dsm + (sbase - smem_u32(dsm)) + ROWSUM_OFF);

    int tid = threadIdx.x, wid = tid >> 5, lane = tid & 31;
    int b = blockIdx.z, bm = blockIdx.y * BM, bn = blockIdx.x * BN;

    if (tid < BM) smrow[tid] = 0.f;

    const __half* Ah = g_qh + (size_t)b * SS * DD;
    const __half* Bh = g_kh + (size_t)b * SS * DD;

    int j = tid & 7;          // 16B chunk within 128B row
    int r0 = tid >> 3;        // 0..31

    #define LOAD_STAGE(SB, K0) do {                                            \
        uint32_t _sb = (SB); int _k0 = (K0);                                   \
        _Pragma("unroll")                                                      \
        for (int it = 0; it < 4; it++) {                                       \
            int r = r0 + it * 32;                                              \
            uint32_t so = SWZ((uint32_t)(r * 128 + j * 16));                   \
            cpa16(_sb + A_OFF + so, Ah + (size_t)(bm + r) * DD + _k0 + j * 8); \
            cpa16(_sb + B_OFF + so, Bh + (size_t)(bn + r) * DD + _k0 + j * 8); \
        }                                                                      \
        asm volatile("cp.async.commit_group;" ::: "memory");                   \
    } while (0)

    float acc[4][4][4];
    #pragma unroll
    for (int i = 0; i < 4; i++)
        #pragma unroll
        for (int n = 0; n < 4; n++)
            #pragma unroll
            for (int c = 0; c < 4; c++) acc[i][n][c] = 0.f;

    int wm = (wid & 1) * 64;          // warp M offset in tile
    int wn = (wid >> 1) * 32;         // warp N offset in tile

    int a_r = (lane & 7) + ((lane >> 3) & 1) * 8;
    int a_k = (lane >> 4) * 16;
    int b_r = (lane & 7) + (lane >> 4) * 8;
    int b_k = ((lane >> 3) & 1) * 16;

    // hoisted swizzled base offsets; kb (bits 5-6) applied per ks via XOR
    uint32_t aoff[4], boff[2];
    #pragma unroll
    for (int mt = 0; mt < 4; mt++)
        aoff[mt] = A_OFF + SWZ((uint32_t)((wm + mt * 16 + a_r) * 128 + a_k));
    #pragma unroll
    for (int bt = 0; bt < 2; bt++)
        boff[bt] = B_OFF + SWZ((uint32_t)((wn + bt * 16 + b_r) * 128 + b_k));

    LOAD_STAGE(sbase, 0);
    LOAD_STAGE(sbase + STAGE, BK);

    for (int kt = 0; kt < KITERS; kt++) {
        if (kt == KITERS - 1) asm volatile("cp.async.wait_group 0;" ::: "memory");
        else                  asm volatile("cp.async.wait_group 1;" ::: "memory");
        __syncthreads();
        uint32_t sb = sbase + (kt & 1) * STAGE;

        #pragma unroll
        for (int ks = 0; ks < 4; ks++) {
            uint32_t kb = ks * 32;        // k16 = 32 bytes, bits 5-6 only
            uint32_t a[4][4], bf[2][4];
            #pragma unroll
            for (int mt = 0; mt < 4; mt++) ldsm4(a[mt], (sb + aoff[mt]) ^ kb);
            #pragma unroll
            for (int bt = 0; bt < 2; bt++) ldsm4(bf[bt], (sb + boff[bt]) ^ kb);
            #pragma unroll
            for (int mt = 0; mt < 4; mt++) {
                #pragma unroll
                for (int nt = 0; nt < 4; nt++) {
                    mma_f16(acc[mt][nt], a[mt], &bf[nt >> 1][(nt & 1) * 2]);
                }
            }
        }
        __syncthreads();
        if (kt + 2 < KITERS) LOAD_STAGE(sbase + (kt & 1) * STAGE, (kt + 2) * BK);
    }

    // epilogue: masked write of attn + fused rowsum
    size_t abase = (size_t)b * SS * SS;
    int qr = lane >> 2, qc = (lane & 3) * 2;
    #pragma unroll
    for (int mt = 0; mt < 4; mt++) {
        int row1 = bm + wm + mt * 16 + qr;
        size_t ro1 = abase + (size_t)row1 * SS;
        size_t ro2 = ro1 + 8 * SS;
        float s1 = 0.f, s2 = 0.f;
        #pragma unroll
        for (int nt = 0; nt < 4; nt++) {
            int col = bn + wn + nt * 8 + qc;
            int2 m1 = *(const int2*)&mask[ro1 + col];
            int2 m2 = *(const int2*)&mask[ro2 + col];
            float2 o1, o2;
            o1.x = m1.x ? 0.f : acc[mt][nt][0];
            o1.y = m1.y ? 0.f : acc[mt][nt][1];
            o2.x = m2.x ? 0.f : acc[mt][nt][2];
            o2.y = m2.y ? 0.f : acc[mt][nt][3];
            s1 += o1.x + o1.y;
            s2 += o2.x + o2.y;
            *(float2*)&attn[ro1 + col] = o1;
            *(float2*)&attn[ro2 + col] = o2;
        }
        s1 += __shfl_xor_sync(0xffffffffu, s1, 1);
        s1 += __shfl_xor_sync(0xffffffffu, s1, 2);
        s2 += __shfl_xor_sync(0xffffffffu, s2, 1);
        s2 += __shfl_xor_sync(0xffffffffu, s2, 2);
        if ((lane & 3) == 0) {
            atomicAdd(&smrow[wm + mt * 16 + qr], s1);
            atomicAdd(&smrow[wm + mt * 16 + qr + 8], s2);
        }
    }
    __syncthreads();
    if (tid < BM) atomicAdd(&g_rowsum[(size_t)b * SS + bm + tid], smrow[tid]);
}

// ---------------------------------------------------------------------------
// output = g_rowsum*w + fc_b + q. One block per (b,s). No attn read.
__global__ void k_out(const float* __restrict__ q,
                      const float* __restrict__ fc_b,
                      float* __restrict__ out) {
    int rid = blockIdx.x;
    float rs = g_rowsum[rid];
    float4 w4 = ((const float4*)g_w)[threadIdx.x];
    float4 b4 = ((const float4*)fc_b)[threadIdx.x];
    float4 q4 = ((const float4*)(q + (size_t)rid * DD))[threadIdx.x];
    float4 o;
    o.x = rs * w4.x + b4.x + q4.x;
    o.y = rs * w4.y + b4.y + q4.y;
    o.z = rs * w4.z + b4.z + q4.z;
    o.w = rs * w4.w + b4.w + q4.w;
    ((float4*)(out + (size_t)rid * DD))[threadIdx.x] = o;
}

// ---------------------------------------------------------------------------
extern "C" void kernel_launch(void* const* d_in, const int* in_sizes, int n_in,
                              void* d_out, int out_size) {
    const float* q    = (const float*)d_in[0];
    const float* kmat = (const float*)d_in[1];
    const int*   mask = (const int*)d_in[3];
    const float* V    = (const float*)d_in[4];
    const float* fc_w = (const float*)d_in[5];
    const float* fc_b = (const float*)d_in[6];
    const float* ln_g = (const float*)d_in[7];
    const float* ln_b = (const float*)d_in[8];

    float* out  = (float*)d_out;
    float* attn = out + OUT_ELEMS;

    cudaFuncSetAttribute(k_gemm, cudaFuncAttributeMaxDynamicSharedMemorySize, SMEM_DYN);

    k_w<<<4, 256>>>(fc_w, V);
    k_ln<<<BB * SS, 256>>>(q, ln_g, ln_b);
    k_conv<<<(BB * SS * DD / 4) / 256, 256>>>(kmat);
    dim3 g(SS / BN, SS / BM, BB);
    k_gemm<<<g, 256, SMEM_DYN>>>(mask, attn);
    k_out<<<BB * SS, 256>>>(q, fc_b, out);
}